// round 15
// baseline (speedup 1.0000x reference)
#include <cuda_runtime.h>
#include <cuda_fp16.h>
#include <cstdint>
#include <cstddef>

// Attend_62534723830373: out = softmax(causal(K V^T / sqrt(128))) @ V  (q unused)
// [2,16,2048,128] fp32. fp16 m16n8k16 flash attention; P stays in registers
// (GEMM1 C-frags pack directly into GEMM2 A-frags), one barrier per iteration.
// R15: register diet (GEMM2 in two d-halves, compressed addr tables) +
// __launch_bounds__(128,4) -> 4 CTAs/SM (16 warps) for latency hiding.

namespace {

constexpr int S  = 2048;
constexpr int D  = 128;
constexpr int BM = 64;
constexpr int BN = 64;
constexpr int NTHREADS = 128;
constexpr float SCALE_F = 0.08838834764831845f;
constexpr size_t NELEM = (size_t)2 * 16 * 2048 * 128;

// fp16 tiles: 256B rows (128 halves). Swizzle: 16B chunks xor (row&7) per 128B block.
constexpr int SK_OFF = 0;                    // K' 64 x 256B = 16KB
constexpr int SV_OFF = 16384;                // V 2 x 64 x 256B = 32KB
constexpr int VBYTES = 16384;
constexpr int SMEM_BYTES = SV_OFF + 2 * VBYTES;   // 49152 -> 4 CTAs/SM (196.6KB)

__device__ __half g_k16[NELEM];
__device__ __half g_v16[NELEM];

__global__ void __launch_bounds__(256) cvt16(const float* __restrict__ K,
                                             const float* __restrict__ V) {
    const size_t i = ((size_t)blockIdx.x * 256 + threadIdx.x) * 4;
    float4 k4 = *reinterpret_cast<const float4*>(K + i);
    float4 v4 = *reinterpret_cast<const float4*>(V + i);
    __half2* ko = reinterpret_cast<__half2*>(g_k16 + i);
    __half2* vo = reinterpret_cast<__half2*>(g_v16 + i);
    ko[0] = __floats2half2_rn(k4.x * SCALE_F, k4.y * SCALE_F);
    ko[1] = __floats2half2_rn(k4.z * SCALE_F, k4.w * SCALE_F);
    vo[0] = __floats2half2_rn(v4.x, v4.y);
    vo[1] = __floats2half2_rn(v4.z, v4.w);
}

__device__ __forceinline__ uint32_t smem_u32(const void* p) {
    uint32_t a;
    asm("{ .reg .u64 t; cvta.to.shared.u64 t, %1; cvt.u32.u64 %0, t; }" : "=r"(a) : "l"(p));
    return a;
}
__device__ __forceinline__ uint32_t packh2(float lo, float hi) {
    uint32_t d;
    asm("cvt.rn.f16x2.f32 %0, %1, %2;" : "=r"(d) : "f"(hi), "f"(lo));
    return d;
}
__device__ __forceinline__ uint32_t swzoff(uint32_t row, uint32_t cb, uint32_t rowb) {
    uint32_t block = cb >> 7, rem = cb & 127;
    uint32_t chunk = rem >> 4, inner = rem & 15;
    return row * rowb + block * 128 + (((chunk ^ (row & 7)) << 4) | inner);
}
__device__ __forceinline__ void ldsm4(uint32_t r[4], uint32_t a) {
    asm volatile("ldmatrix.sync.aligned.m8n8.x4.shared.b16 {%0,%1,%2,%3}, [%4];"
                 : "=r"(r[0]), "=r"(r[1]), "=r"(r[2]), "=r"(r[3]) : "r"(a));
}
__device__ __forceinline__ void ldsm4t(uint32_t r[4], uint32_t a) {
    asm volatile("ldmatrix.sync.aligned.m8n8.x4.trans.shared.b16 {%0,%1,%2,%3}, [%4];"
                 : "=r"(r[0]), "=r"(r[1]), "=r"(r[2]), "=r"(r[3]) : "r"(a));
}
__device__ __forceinline__ void cpasync16(uint32_t dst, const void* src) {
    asm volatile("cp.async.cg.shared.global [%0], [%1], 16;" :: "r"(dst), "l"(src) : "memory");
}
__device__ __forceinline__ void cpasync_commit() {
    asm volatile("cp.async.commit_group;" ::: "memory");
}
__device__ __forceinline__ void cpasync_wait0() {
    asm volatile("cp.async.wait_group 0;" ::: "memory");
}
__device__ __forceinline__ void mma16(float* c,
                                      uint32_t a0, uint32_t a1, uint32_t a2, uint32_t a3,
                                      uint32_t b0, uint32_t b1) {
    asm volatile(
        "mma.sync.aligned.m16n8k16.row.col.f32.f16.f16.f32 "
        "{%0,%1,%2,%3}, {%4,%5,%6,%7}, {%8,%9}, {%0,%1,%2,%3};"
        : "+f"(c[0]), "+f"(c[1]), "+f"(c[2]), "+f"(c[3])
        : "r"(a0), "r"(a1), "r"(a2), "r"(a3), "r"(b0), "r"(b1));
}

__global__ __launch_bounds__(NTHREADS, 4)
void fa_regP4(float* __restrict__ Og) {
    extern __shared__ __align__(1024) char smem[];
    const uint32_t sb = smem_u32(smem);
    const int tid  = threadIdx.x;
    const int wid  = tid >> 5;
    const int lane = tid & 31;
    const int g    = lane >> 2;
    const int tg   = lane & 3;
    const int mat  = lane >> 3;
    const int rr   = lane & 7;

    const int bh = blockIdx.y;
    const int qb = (int)gridDim.x - 1 - (int)blockIdx.x;   // longest first

    const __half* K16 = g_k16 + (size_t)bh * S * D;
    const __half* V16 = g_v16 + (size_t)bh * S * D;
    float*        Oh  = Og   + (size_t)bh * S * D;

    const int ri  = wid * 16;             // warp's query rows
    const int gi0 = qb * BM + ri + g;     // thread's global rows
    const int gi1 = gi0 + 8;

    const uint32_t rowA = (uint32_t)(((mat & 1) << 3) + rr);
    const uint32_t cbA  = (uint32_t)((mat >> 1) << 4);
    const uint32_t rowB = (uint32_t)(((mat >> 1) << 3) + rr);
    const uint32_t cbB  = (uint32_t)((mat & 1) << 4);

    // ---- compressed loop-invariant address tables ----
    uint32_t swA1[4], swB1[4];             // GEMM1 kt remainders (256B rows)
    #pragma unroll
    for (int r = 0; r < 4; ++r) {
        swA1[r] = swzoff(rowA, (uint32_t)r * 32 + cbA, 256) - rowA * 256;
        swB1[r] = swzoff(rowB, (uint32_t)r * 32 + cbB, 256) - rowB * 256;
    }
    const uint32_t ka = sb + SK_OFF + (uint32_t)(ri + rowA) * 256;   // GEMM1 A (K')
    const uint32_t vb0 = rowB * 256;                                 // GEMM1 B rows (+q*4096)
    // GEMM2 B (V j-major, trans): periodic-4 remainder; + (dp>>2)*128 immediate
    uint32_t remVT4[4];
    #pragma unroll
    for (int q = 0; q < 4; ++q)
        remVT4[q] = swzoff(rowA, (uint32_t)(q * 32) + cbA, 256) - rowA * 256;

    // tile-load mapping (cp.async): thread owns row vr, 128B block vh
    const int vr  = tid >> 1;
    const int vh  = tid & 1;
    const uint32_t vrl = (uint32_t)(vr & 7);
    const uint32_t vstBase = (uint32_t)vr * 256 + (uint32_t)vh * 128;

    // ---- prologue: cp.async K' block + V tile 0 ----
    {
        const __half* ks = K16 + (size_t)(qb * BM + vr) * D + vh * 64;
        const __half* vs = V16 + (size_t)vr * D + vh * 64;
        #pragma unroll
        for (int q = 0; q < 8; ++q) {
            const uint32_t off = vstBase + (uint32_t)(((uint32_t)q ^ vrl) << 4);
            cpasync16(sb + SK_OFF + off, ks + q * 8);
            cpasync16(sb + SV_OFF + off, vs + q * 8);
        }
        cpasync_commit();
    }

    float oacc[16][4];
    #pragma unroll
    for (int dg = 0; dg < 16; ++dg) {
        oacc[dg][0] = 0.f; oacc[dg][1] = 0.f; oacc[dg][2] = 0.f; oacc[dg][3] = 0.f;
    }
    float ls0 = 0.f, ls1 = 0.f;

    const __half* gv = V16 + (size_t)(BN + vr) * D + vh * 64;   // V(jb+1) source

    cpasync_wait0();
    __syncthreads();   // K' + V0 visible

    for (int jb = 0; jb <= qb; ++jb) {
        const int cur = jb & 1;
        const uint32_t svc = sb + SV_OFF + (uint32_t)cur * VBYTES;

        // ---- prefetch V(jb+1) ----
        if (jb < qb) {
            const uint32_t dbase = sb + SV_OFF + (uint32_t)(cur ^ 1) * VBYTES + vstBase;
            #pragma unroll
            for (int q = 0; q < 8; ++q)
                cpasync16(dbase + (uint32_t)(((uint32_t)q ^ vrl) << 4), gv + q * 8);
            cpasync_commit();
            gv += (size_t)BN * D;
        }

        // ---- GEMM1: S[16i x 64j] = K'[16i x 128d] * V^T ----
        float sacc[8][4];
        #pragma unroll
        for (int jt = 0; jt < 8; ++jt) {
            sacc[jt][0] = 0.f; sacc[jt][1] = 0.f; sacc[jt][2] = 0.f; sacc[jt][3] = 0.f;
        }
        #pragma unroll
        for (int kt = 0; kt < 8; ++kt) {
            const uint32_t offA = swA1[kt & 3] + (uint32_t)((kt >> 2) * 128);
            const uint32_t offB = swB1[kt & 3] + (uint32_t)((kt >> 2) * 128);
            uint32_t a[4], b[4][4];
            ldsm4(a, ka + offA);
            #pragma unroll
            for (int q = 0; q < 4; ++q)
                ldsm4(b[q], svc + vb0 + (uint32_t)(q * 4096) + offB);
            #pragma unroll
            for (int jt = 0; jt < 8; ++jt)
                mma16(sacc[jt], a[0], a[1], a[2], a[3],
                      b[jt >> 1][(jt & 1) * 2], b[jt >> 1][(jt & 1) * 2 + 1]);
        }

        // ---- softmax in registers: mask, exp, lsum; pack C-frags -> A-frags ----
        uint32_t pvA[8], pvB[8];
        #pragma unroll
        for (int jt = 0; jt < 8; ++jt) {
            const int jc = jb * BN + jt * 8 + 2 * tg;
            float p00 = (jc     <= gi0) ? __expf(sacc[jt][0]) : 0.f;
            float p01 = (jc + 1 <= gi0) ? __expf(sacc[jt][1]) : 0.f;
            float p10 = (jc     <= gi1) ? __expf(sacc[jt][2]) : 0.f;
            float p11 = (jc + 1 <= gi1) ? __expf(sacc[jt][3]) : 0.f;
            ls0 += p00 + p01;
            ls1 += p10 + p11;
            pvA[jt] = packh2(p00, p01);
            pvB[jt] = packh2(p10, p11);
        }

        // ---- GEMM2: O[16i x 128d] += P * V, two d-halves (bV = 16 regs live) ----
        const uint32_t vtb = svc + rowA * 256;
        #pragma unroll
        for (int dh = 0; dh < 2; ++dh) {
            #pragma unroll
            for (int kt = 0; kt < 4; ++kt) {
                uint32_t bV[4][4];
                #pragma unroll
                for (int q = 0; q < 4; ++q)
                    ldsm4t(bV[q], vtb + (uint32_t)kt * 4096 +
                                  (uint32_t)(dh * 128) + remVT4[q]);
                const uint32_t a0 = pvA[2 * kt],     a1 = pvB[2 * kt];
                const uint32_t a2 = pvA[2 * kt + 1], a3 = pvB[2 * kt + 1];
                #pragma unroll
                for (int dq = 0; dq < 8; ++dq)
                    mma16(oacc[dh * 8 + dq], a0, a1, a2, a3,
                          bV[dq >> 1][(dq & 1) * 2], bV[dq >> 1][(dq & 1) * 2 + 1]);
            }
        }

        cpasync_wait0();
        __syncthreads();   // next V landed; all reads of V[cur] done
    }

    // ---- epilogue: lsum reduce within quad ----
    ls0 += __shfl_xor_sync(0xffffffffu, ls0, 1);
    ls0 += __shfl_xor_sync(0xffffffffu, ls0, 2);
    ls1 += __shfl_xor_sync(0xffffffffu, ls1, 1);
    ls1 += __shfl_xor_sync(0xffffffffu, ls1, 2);
    const float inv0 = 1.f / ls0;
    const float inv1 = 1.f / ls1;

    float* o0 = Oh + (size_t)gi0 * D + 2 * tg;
    float* o1 = Oh + (size_t)gi1 * D + 2 * tg;
    #pragma unroll
    for (int dg = 0; dg < 16; ++dg) {
        float2 w0 = make_float2(oacc[dg][0] * inv0, oacc[dg][1] * inv0);
        float2 w1 = make_float2(oacc[dg][2] * inv1, oacc[dg][3] * inv1);
        *reinterpret_cast<float2*>(o0 + dg * 8) = w0;
        *reinterpret_cast<float2*>(o1 + dg * 8) = w1;
    }
}

}  // namespace

extern "C" void kernel_launch(void* const* d_in, const int* /*in_sizes*/, int /*n_in*/,
                              void* d_out, int /*out_size*/) {
    // inputs: d_in[0]=q (unused by reference), d_in[1]=k, d_in[2]=v
    const float* k = reinterpret_cast<const float*>(d_in[1]);
    const float* v = reinterpret_cast<const float*>(d_in[2]);
    float* o = reinterpret_cast<float*>(d_out);

    cvt16<<<(unsigned)(NELEM / 4 / 256), 256>>>(k, v);

    cudaFuncSetAttribute(fa_regP4,
                         cudaFuncAttributeMaxDynamicSharedMemorySize, SMEM_BYTES);
    dim3 grid(S / BM, 32);
    fa_regP4<<<grid, NTHREADS, SMEM_BYTES>>>(o);
}

// round 16
// speedup vs baseline: 1.2610x; 1.2610x over previous
#include <cuda_runtime.h>
#include <cuda_fp16.h>
#include <cstdint>
#include <cstddef>

// Attend_62534723830373: out = softmax(causal(K V^T / sqrt(128))) @ V  (q unused)
// [2,16,2048,128] fp32. fp16 m16n8k16 flash attention; P stays in registers
// (GEMM1 C-frags pack directly into GEMM2 A-frags); one barrier per iteration.
// R16 = R14 (3 CTAs/SM) + diagonal-split softmax (mask only on jb==qb) +
// 3-stage V ring with prefetch distance 2 (end-of-iter wait never blocks).

namespace {

constexpr int S  = 2048;
constexpr int D  = 128;
constexpr int BM = 64;
constexpr int BN = 64;
constexpr int NTHREADS = 128;
constexpr float SCALE_F = 0.08838834764831845f;
constexpr size_t NELEM = (size_t)2 * 16 * 2048 * 128;

// fp16 tiles: 256B rows. Swizzle: 16B chunks xor (row&7) within each 128B block.
constexpr int SK_OFF = 0;                    // K' 64 x 256B = 16KB
constexpr int SV_OFF = 16384;                // V ring: 3 x 64 x 256B = 48KB
constexpr int VBYTES = 16384;
constexpr int SMEM_BYTES = SV_OFF + 3 * VBYTES;   // 65536 -> 3 CTAs/SM (192KB)

__device__ __half g_k16[NELEM];
__device__ __half g_v16[NELEM];

__global__ void __launch_bounds__(256) cvt16(const float* __restrict__ K,
                                             const float* __restrict__ V) {
    const size_t i = ((size_t)blockIdx.x * 256 + threadIdx.x) * 4;
    float4 k4 = *reinterpret_cast<const float4*>(K + i);
    float4 v4 = *reinterpret_cast<const float4*>(V + i);
    __half2* ko = reinterpret_cast<__half2*>(g_k16 + i);
    __half2* vo = reinterpret_cast<__half2*>(g_v16 + i);
    ko[0] = __floats2half2_rn(k4.x * SCALE_F, k4.y * SCALE_F);
    ko[1] = __floats2half2_rn(k4.z * SCALE_F, k4.w * SCALE_F);
    vo[0] = __floats2half2_rn(v4.x, v4.y);
    vo[1] = __floats2half2_rn(v4.z, v4.w);
}

__device__ __forceinline__ uint32_t smem_u32(const void* p) {
    uint32_t a;
    asm("{ .reg .u64 t; cvta.to.shared.u64 t, %1; cvt.u32.u64 %0, t; }" : "=r"(a) : "l"(p));
    return a;
}
__device__ __forceinline__ uint32_t packh2(float lo, float hi) {
    uint32_t d;
    asm("cvt.rn.f16x2.f32 %0, %1, %2;" : "=r"(d) : "f"(hi), "f"(lo));
    return d;
}
__device__ __forceinline__ uint32_t swzoff(uint32_t row, uint32_t cb, uint32_t rowb) {
    uint32_t block = cb >> 7, rem = cb & 127;
    uint32_t chunk = rem >> 4, inner = rem & 15;
    return row * rowb + block * 128 + (((chunk ^ (row & 7)) << 4) | inner);
}
__device__ __forceinline__ void ldsm4(uint32_t r[4], uint32_t a) {
    asm volatile("ldmatrix.sync.aligned.m8n8.x4.shared.b16 {%0,%1,%2,%3}, [%4];"
                 : "=r"(r[0]), "=r"(r[1]), "=r"(r[2]), "=r"(r[3]) : "r"(a));
}
__device__ __forceinline__ void ldsm4t(uint32_t r[4], uint32_t a) {
    asm volatile("ldmatrix.sync.aligned.m8n8.x4.trans.shared.b16 {%0,%1,%2,%3}, [%4];"
                 : "=r"(r[0]), "=r"(r[1]), "=r"(r[2]), "=r"(r[3]) : "r"(a));
}
__device__ __forceinline__ void cpasync16(uint32_t dst, const void* src) {
    asm volatile("cp.async.cg.shared.global [%0], [%1], 16;" :: "r"(dst), "l"(src) : "memory");
}
__device__ __forceinline__ void cpasync_commit() {
    asm volatile("cp.async.commit_group;" ::: "memory");
}
__device__ __forceinline__ void cpasync_wait0() {
    asm volatile("cp.async.wait_group 0;" ::: "memory");
}
__device__ __forceinline__ void cpasync_wait1() {
    asm volatile("cp.async.wait_group 1;" ::: "memory");
}
__device__ __forceinline__ void mma16(float* c,
                                      uint32_t a0, uint32_t a1, uint32_t a2, uint32_t a3,
                                      uint32_t b0, uint32_t b1) {
    asm volatile(
        "mma.sync.aligned.m16n8k16.row.col.f32.f16.f16.f32 "
        "{%0,%1,%2,%3}, {%4,%5,%6,%7}, {%8,%9}, {%0,%1,%2,%3};"
        : "+f"(c[0]), "+f"(c[1]), "+f"(c[2]), "+f"(c[3])
        : "r"(a0), "r"(a1), "r"(a2), "r"(a3), "r"(b0), "r"(b1));
}

__global__ __launch_bounds__(NTHREADS, 3)
void fa_r16(float* __restrict__ Og) {
    extern __shared__ __align__(1024) char smem[];
    const uint32_t sb = smem_u32(smem);
    const int tid  = threadIdx.x;
    const int wid  = tid >> 5;
    const int lane = tid & 31;
    const int g    = lane >> 2;
    const int tg   = lane & 3;
    const int mat  = lane >> 3;
    const int rr   = lane & 7;

    const int bh = blockIdx.y;
    const int qb = (int)gridDim.x - 1 - (int)blockIdx.x;   // longest first

    const __half* K16 = g_k16 + (size_t)bh * S * D;
    const __half* V16 = g_v16 + (size_t)bh * S * D;
    float*        Oh  = Og   + (size_t)bh * S * D;

    const int ri  = wid * 16;             // warp's query rows
    const int gi0 = qb * BM + ri + g;     // thread's global rows
    const int gi1 = gi0 + 8;

    const uint32_t rowA = (uint32_t)(((mat & 1) << 3) + rr);
    const uint32_t cbA  = (uint32_t)((mat >> 1) << 4);
    const uint32_t rowB = (uint32_t)(((mat >> 1) << 3) + rr);
    const uint32_t cbB  = (uint32_t)((mat & 1) << 4);

    // ---- loop-invariant address tables (as R14) ----
    uint32_t swA1[4], swB1[4];
    #pragma unroll
    for (int r = 0; r < 4; ++r) {
        swA1[r] = swzoff(rowA, (uint32_t)r * 32 + cbA, 256) - rowA * 256;
        swB1[r] = swzoff(rowB, (uint32_t)r * 32 + cbB, 256) - rowB * 256;
    }
    const uint32_t ka = sb + SK_OFF + (uint32_t)(ri + rowA) * 256;   // GEMM1 A (K')
    uint32_t vbC[4];                                                  // GEMM1 B rows
    #pragma unroll
    for (int q = 0; q < 4; ++q)
        vbC[q] = (uint32_t)(q * 16 + rowB) * 256;
    uint32_t remVT[8];                                                // GEMM2 B (trans)
    #pragma unroll
    for (int dp = 0; dp < 8; ++dp)
        remVT[dp] = swzoff(rowA, (uint32_t)(dp * 32) + cbA, 256) - rowA * 256;

    // tile-load mapping (cp.async): thread owns row vr, 128B block vh
    const int vr  = tid >> 1;
    const int vh  = tid & 1;
    const uint32_t vrl = (uint32_t)(vr & 7);
    const uint32_t vstBase = (uint32_t)vr * 256 + (uint32_t)vh * 128;

    // ---- prologue: K' + V0 (group 0); V1 (group 1) ----
    {
        const __half* ks = K16 + (size_t)(qb * BM + vr) * D + vh * 64;
        const __half* vs = V16 + (size_t)vr * D + vh * 64;
        #pragma unroll
        for (int q = 0; q < 8; ++q) {
            const uint32_t off = vstBase + (uint32_t)(((uint32_t)q ^ vrl) << 4);
            cpasync16(sb + SK_OFF + off, ks + q * 8);
            cpasync16(sb + SV_OFF + off, vs + q * 8);
        }
        cpasync_commit();
        if (qb >= 1) {
            const __half* vs1 = vs + (size_t)BN * D;
            #pragma unroll
            for (int q = 0; q < 8; ++q)
                cpasync16(sb + SV_OFF + VBYTES + vstBase +
                          (uint32_t)(((uint32_t)q ^ vrl) << 4), vs1 + q * 8);
            cpasync_commit();
        }
    }

    float oacc[16][4];
    #pragma unroll
    for (int dg = 0; dg < 16; ++dg) {
        oacc[dg][0] = 0.f; oacc[dg][1] = 0.f; oacc[dg][2] = 0.f; oacc[dg][3] = 0.f;
    }
    float ls0 = 0.f, ls1 = 0.f;

    const __half* gv = V16 + (size_t)(2 * BN + vr) * D + vh * 64;   // V(jb+2) source

    if (qb >= 1) cpasync_wait1(); else cpasync_wait0();
    __syncthreads();   // K' + V0 visible

    int cur = 0;
    for (int jb = 0; jb <= qb; ++jb) {
        const uint32_t svc = sb + SV_OFF + (uint32_t)cur * VBYTES;
        const bool deep = (jb + 2 <= qb);

        // ---- GEMM1: S[16i x 64j] = K'[16i x 128d] * V^T ----
        float sacc[8][4];
        #pragma unroll
        for (int jt = 0; jt < 8; ++jt) {
            sacc[jt][0] = 0.f; sacc[jt][1] = 0.f; sacc[jt][2] = 0.f; sacc[jt][3] = 0.f;
        }
        #pragma unroll
        for (int kt = 0; kt < 8; ++kt) {
            const uint32_t offA = swA1[kt & 3] + (uint32_t)((kt >> 2) * 128);
            const uint32_t offB = swB1[kt & 3] + (uint32_t)((kt >> 2) * 128);
            uint32_t a[4], b[4][4];
            ldsm4(a, ka + offA);
            #pragma unroll
            for (int q = 0; q < 4; ++q)
                ldsm4(b[q], svc + vbC[q] + offB);
            #pragma unroll
            for (int jt = 0; jt < 8; ++jt)
                mma16(sacc[jt], a[0], a[1], a[2], a[3],
                      b[jt >> 1][(jt & 1) * 2], b[jt >> 1][(jt & 1) * 2 + 1]);
        }

        // ---- prefetch V(jb+2) into buffer (cur+2)%3 (distance 2) ----
        if (deep) {
            int pbuf = cur + 2; if (pbuf >= 3) pbuf -= 3;
            const uint32_t dbase = sb + SV_OFF + (uint32_t)pbuf * VBYTES + vstBase;
            #pragma unroll
            for (int q = 0; q < 8; ++q)
                cpasync16(dbase + (uint32_t)(((uint32_t)q ^ vrl) << 4), gv + q * 8);
            cpasync_commit();
            gv += (size_t)BN * D;
        }

        // ---- softmax in registers (diagonal split); pack C-frags -> A-frags ----
        uint32_t pvA[8], pvB[8];
        if (jb != qb) {
            // provably unmasked: jc <= jb*64+63 < qb*64 <= gi0
            #pragma unroll
            for (int jt = 0; jt < 8; ++jt) {
                const float p00 = __expf(sacc[jt][0]);
                const float p01 = __expf(sacc[jt][1]);
                const float p10 = __expf(sacc[jt][2]);
                const float p11 = __expf(sacc[jt][3]);
                ls0 += p00 + p01;
                ls1 += p10 + p11;
                pvA[jt] = packh2(p00, p01);
                pvB[jt] = packh2(p10, p11);
            }
        } else {
            #pragma unroll
            for (int jt = 0; jt < 8; ++jt) {
                const int jc = jb * BN + jt * 8 + 2 * tg;
                float p00 = (jc     <= gi0) ? __expf(sacc[jt][0]) : 0.f;
                float p01 = (jc + 1 <= gi0) ? __expf(sacc[jt][1]) : 0.f;
                float p10 = (jc     <= gi1) ? __expf(sacc[jt][2]) : 0.f;
                float p11 = (jc + 1 <= gi1) ? __expf(sacc[jt][3]) : 0.f;
                ls0 += p00 + p01;
                ls1 += p10 + p11;
                pvA[jt] = packh2(p00, p01);
                pvB[jt] = packh2(p10, p11);
            }
        }

        // ---- GEMM2: O[16i x 128d] += P[16i x 64j] * V[64j x 128d] ----
        const uint32_t vtb = svc + rowA * 256;
        #pragma unroll
        for (int kt = 0; kt < 4; ++kt) {
            uint32_t bV[8][4];
            #pragma unroll
            for (int dp = 0; dp < 8; ++dp)
                ldsm4t(bV[dp], vtb + (uint32_t)kt * 4096 + remVT[dp]);
            const uint32_t a0 = pvA[2 * kt],     a1 = pvB[2 * kt];
            const uint32_t a2 = pvA[2 * kt + 1], a3 = pvB[2 * kt + 1];
            #pragma unroll
            for (int dg = 0; dg < 16; ++dg)
                mma16(oacc[dg], a0, a1, a2, a3,
                      bV[dg >> 1][(dg & 1) * 2], bV[dg >> 1][(dg & 1) * 2 + 1]);
        }

        // ---- V(jb+1) must be resident for the next iteration ----
        if (deep) cpasync_wait1();   // newest (V(jb+2)) may stay in flight
        else      cpasync_wait0();
        __syncthreads();

        if (++cur == 3) cur = 0;
    }

    // ---- epilogue: lsum reduce within quad (rows complete in-warp) ----
    ls0 += __shfl_xor_sync(0xffffffffu, ls0, 1);
    ls0 += __shfl_xor_sync(0xffffffffu, ls0, 2);
    ls1 += __shfl_xor_sync(0xffffffffu, ls1, 1);
    ls1 += __shfl_xor_sync(0xffffffffu, ls1, 2);
    const float inv0 = 1.f / ls0;
    const float inv1 = 1.f / ls1;

    float* o0 = Oh + (size_t)gi0 * D + 2 * tg;
    float* o1 = Oh + (size_t)gi1 * D + 2 * tg;
    #pragma unroll
    for (int dg = 0; dg < 16; ++dg) {
        float2 w0 = make_float2(oacc[dg][0] * inv0, oacc[dg][1] * inv0);
        float2 w1 = make_float2(oacc[dg][2] * inv1, oacc[dg][3] * inv1);
        *reinterpret_cast<float2*>(o0 + dg * 8) = w0;
        *reinterpret_cast<float2*>(o1 + dg * 8) = w1;
    }
}

}  // namespace

extern "C" void kernel_launch(void* const* d_in, const int* /*in_sizes*/, int /*n_in*/,
                              void* d_out, int /*out_size*/) {
    // inputs: d_in[0]=q (unused by reference), d_in[1]=k, d_in[2]=v
    const float* k = reinterpret_cast<const float*>(d_in[1]);
    const float* v = reinterpret_cast<const float*>(d_in[2]);
    float* o = reinterpret_cast<float*>(d_out);

    cvt16<<<(unsigned)(NELEM / 4 / 256), 256>>>(k, v);

    cudaFuncSetAttribute(fa_r16,
                         cudaFuncAttributeMaxDynamicSharedMemorySize, SMEM_BYTES);
    dim3 grid(S / BM, 32);
    fa_r16<<<grid, NTHREADS, SMEM_BYTES>>>(o);
}

// round 17
// speedup vs baseline: 1.2884x; 1.0217x over previous
#include <cuda_runtime.h>
#include <cuda_fp16.h>
#include <cstdint>
#include <cstddef>

// Attend_62534723830373: out = softmax(causal(K V^T / sqrt(128))) @ V  (q unused)
// [2,16,2048,128] fp32. fp16 m16n8k16 flash attention; P stays in registers
// (GEMM1 C-frags pack directly into GEMM2 A-frags); one barrier per iteration;
// 3-stage V ring with prefetch distance 2; diagonal-split softmax.
// R17: prepass converts ONLY V (K rows have zero cross-CTA reuse, so each CTA
// converts its own K' tile in the prologue, overlapped with the V cp.async).

namespace {

constexpr int S  = 2048;
constexpr int D  = 128;
constexpr int BM = 64;
constexpr int BN = 64;
constexpr int NTHREADS = 128;
constexpr float SCALE_F = 0.08838834764831845f;
constexpr size_t NELEM = (size_t)2 * 16 * 2048 * 128;

// fp16 tiles: 256B rows. Swizzle: 16B chunks xor (row&7) within each 128B block.
constexpr int SK_OFF = 0;                    // K' 64 x 256B = 16KB
constexpr int SV_OFF = 16384;                // V ring: 3 x 64 x 256B = 48KB
constexpr int VBYTES = 16384;
constexpr int SMEM_BYTES = SV_OFF + 3 * VBYTES;   // 65536 -> 3 CTAs/SM (192KB)

__device__ __half g_v16[NELEM];

// ---- pre-pass: V fp32 -> fp16 only ----
__global__ void __launch_bounds__(256) cvt16v(const float* __restrict__ V) {
    const size_t i = ((size_t)blockIdx.x * 256 + threadIdx.x) * 4;
    float4 v4 = *reinterpret_cast<const float4*>(V + i);
    __half2* vo = reinterpret_cast<__half2*>(g_v16 + i);
    vo[0] = __floats2half2_rn(v4.x, v4.y);
    vo[1] = __floats2half2_rn(v4.z, v4.w);
}

__device__ __forceinline__ uint32_t smem_u32(const void* p) {
    uint32_t a;
    asm("{ .reg .u64 t; cvta.to.shared.u64 t, %1; cvt.u32.u64 %0, t; }" : "=r"(a) : "l"(p));
    return a;
}
__device__ __forceinline__ uint32_t packh2(float lo, float hi) {
    uint32_t d;
    asm("cvt.rn.f16x2.f32 %0, %1, %2;" : "=r"(d) : "f"(hi), "f"(lo));
    return d;
}
__device__ __forceinline__ uint32_t swzoff(uint32_t row, uint32_t cb, uint32_t rowb) {
    uint32_t block = cb >> 7, rem = cb & 127;
    uint32_t chunk = rem >> 4, inner = rem & 15;
    return row * rowb + block * 128 + (((chunk ^ (row & 7)) << 4) | inner);
}
__device__ __forceinline__ void ldsm4(uint32_t r[4], uint32_t a) {
    asm volatile("ldmatrix.sync.aligned.m8n8.x4.shared.b16 {%0,%1,%2,%3}, [%4];"
                 : "=r"(r[0]), "=r"(r[1]), "=r"(r[2]), "=r"(r[3]) : "r"(a));
}
__device__ __forceinline__ void ldsm4t(uint32_t r[4], uint32_t a) {
    asm volatile("ldmatrix.sync.aligned.m8n8.x4.trans.shared.b16 {%0,%1,%2,%3}, [%4];"
                 : "=r"(r[0]), "=r"(r[1]), "=r"(r[2]), "=r"(r[3]) : "r"(a));
}
__device__ __forceinline__ void sts128(uint32_t a, uint32_t x, uint32_t y,
                                       uint32_t z, uint32_t w) {
    asm volatile("st.shared.v4.b32 [%0], {%1,%2,%3,%4};"
                 :: "r"(a), "r"(x), "r"(y), "r"(z), "r"(w));
}
__device__ __forceinline__ void cpasync16(uint32_t dst, const void* src) {
    asm volatile("cp.async.cg.shared.global [%0], [%1], 16;" :: "r"(dst), "l"(src) : "memory");
}
__device__ __forceinline__ void cpasync_commit() {
    asm volatile("cp.async.commit_group;" ::: "memory");
}
__device__ __forceinline__ void cpasync_wait0() {
    asm volatile("cp.async.wait_group 0;" ::: "memory");
}
__device__ __forceinline__ void cpasync_wait1() {
    asm volatile("cp.async.wait_group 1;" ::: "memory");
}
__device__ __forceinline__ void mma16(float* c,
                                      uint32_t a0, uint32_t a1, uint32_t a2, uint32_t a3,
                                      uint32_t b0, uint32_t b1) {
    asm volatile(
        "mma.sync.aligned.m16n8k16.row.col.f32.f16.f16.f32 "
        "{%0,%1,%2,%3}, {%4,%5,%6,%7}, {%8,%9}, {%0,%1,%2,%3};"
        : "+f"(c[0]), "+f"(c[1]), "+f"(c[2]), "+f"(c[3])
        : "r"(a0), "r"(a1), "r"(a2), "r"(a3), "r"(b0), "r"(b1));
}

__global__ __launch_bounds__(NTHREADS, 3)
void fa_r17(const float* __restrict__ Kg, float* __restrict__ Og) {
    extern __shared__ __align__(1024) char smem[];
    const uint32_t sb = smem_u32(smem);
    const int tid  = threadIdx.x;
    const int wid  = tid >> 5;
    const int lane = tid & 31;
    const int g    = lane >> 2;
    const int tg   = lane & 3;
    const int mat  = lane >> 3;
    const int rr   = lane & 7;

    const int bh = blockIdx.y;
    const int qb = (int)gridDim.x - 1 - (int)blockIdx.x;   // longest first

    const float*  Kh  = Kg    + (size_t)bh * S * D;
    const __half* V16 = g_v16 + (size_t)bh * S * D;
    float*        Oh  = Og    + (size_t)bh * S * D;

    const int ri  = wid * 16;             // warp's query rows
    const int gi0 = qb * BM + ri + g;     // thread's global rows
    const int gi1 = gi0 + 8;

    const uint32_t rowA = (uint32_t)(((mat & 1) << 3) + rr);
    const uint32_t cbA  = (uint32_t)((mat >> 1) << 4);
    const uint32_t rowB = (uint32_t)(((mat >> 1) << 3) + rr);
    const uint32_t cbB  = (uint32_t)((mat & 1) << 4);

    // ---- loop-invariant address tables (as R16) ----
    uint32_t swA1[4], swB1[4];
    #pragma unroll
    for (int r = 0; r < 4; ++r) {
        swA1[r] = swzoff(rowA, (uint32_t)r * 32 + cbA, 256) - rowA * 256;
        swB1[r] = swzoff(rowB, (uint32_t)r * 32 + cbB, 256) - rowB * 256;
    }
    const uint32_t ka = sb + SK_OFF + (uint32_t)(ri + rowA) * 256;   // GEMM1 A (K')
    uint32_t vbC[4];                                                  // GEMM1 B rows
    #pragma unroll
    for (int q = 0; q < 4; ++q)
        vbC[q] = (uint32_t)(q * 16 + rowB) * 256;
    uint32_t remVT[8];                                                // GEMM2 B (trans)
    #pragma unroll
    for (int dp = 0; dp < 8; ++dp)
        remVT[dp] = swzoff(rowA, (uint32_t)(dp * 32) + cbA, 256) - rowA * 256;

    // tile-load mapping: thread owns row vr, 128B block vh
    const int vr  = tid >> 1;
    const int vh  = tid & 1;
    const uint32_t vrl = (uint32_t)(vr & 7);
    const uint32_t vstBase = (uint32_t)vr * 256 + (uint32_t)vh * 128;

    // ---- prologue: V0 (group 0), V1 (group 1) via cp.async; K' converted here ----
    {
        const __half* vs = V16 + (size_t)vr * D + vh * 64;
        #pragma unroll
        for (int q = 0; q < 8; ++q)
            cpasync16(sb + SV_OFF + vstBase + (uint32_t)(((uint32_t)q ^ vrl) << 4),
                      vs + q * 8);
        cpasync_commit();
        if (qb >= 1) {
            const __half* vs1 = vs + (size_t)BN * D;
            #pragma unroll
            for (int q = 0; q < 8; ++q)
                cpasync16(sb + SV_OFF + VBYTES + vstBase +
                          (uint32_t)(((uint32_t)q ^ vrl) << 4), vs1 + q * 8);
            cpasync_commit();
        }
        // K' tile: fp32 load, scale, rn-cvt to fp16 smem (identical math to the
        // old prepass; overlapped with the V cp.async above)
        const float4* ks = reinterpret_cast<const float4*>(
            Kh + (size_t)(qb * BM + vr) * D + vh * 64);
        #pragma unroll
        for (int q = 0; q < 8; ++q) {
            float4 x0 = ks[2 * q], x1 = ks[2 * q + 1];
            sts128(sb + SK_OFF + vstBase + (uint32_t)(((uint32_t)q ^ vrl) << 4),
                   packh2(x0.x * SCALE_F, x0.y * SCALE_F),
                   packh2(x0.z * SCALE_F, x0.w * SCALE_F),
                   packh2(x1.x * SCALE_F, x1.y * SCALE_F),
                   packh2(x1.z * SCALE_F, x1.w * SCALE_F));
        }
    }

    float oacc[16][4];
    #pragma unroll
    for (int dg = 0; dg < 16; ++dg) {
        oacc[dg][0] = 0.f; oacc[dg][1] = 0.f; oacc[dg][2] = 0.f; oacc[dg][3] = 0.f;
    }
    float ls0 = 0.f, ls1 = 0.f;

    const __half* gv = V16 + (size_t)(2 * BN + vr) * D + vh * 64;   // V(jb+2) source

    if (qb >= 1) cpasync_wait1(); else cpasync_wait0();
    __syncthreads();   // K' + V0 visible

    int cur = 0;
    for (int jb = 0; jb <= qb; ++jb) {
        const uint32_t svc = sb + SV_OFF + (uint32_t)cur * VBYTES;
        const bool deep = (jb + 2 <= qb);

        // ---- GEMM1: S[16i x 64j] = K'[16i x 128d] * V^T ----
        float sacc[8][4];
        #pragma unroll
        for (int jt = 0; jt < 8; ++jt) {
            sacc[jt][0] = 0.f; sacc[jt][1] = 0.f; sacc[jt][2] = 0.f; sacc[jt][3] = 0.f;
        }
        #pragma unroll
        for (int kt = 0; kt < 8; ++kt) {
            const uint32_t offA = swA1[kt & 3] + (uint32_t)((kt >> 2) * 128);
            const uint32_t offB = swB1[kt & 3] + (uint32_t)((kt >> 2) * 128);
            uint32_t a[4], b[4][4];
            ldsm4(a, ka + offA);
            #pragma unroll
            for (int q = 0; q < 4; ++q)
                ldsm4(b[q], svc + vbC[q] + offB);
            #pragma unroll
            for (int jt = 0; jt < 8; ++jt)
                mma16(sacc[jt], a[0], a[1], a[2], a[3],
                      b[jt >> 1][(jt & 1) * 2], b[jt >> 1][(jt & 1) * 2 + 1]);
        }

        // ---- prefetch V(jb+2) into buffer (cur+2)%3 (distance 2) ----
        if (deep) {
            int pbuf = cur + 2; if (pbuf >= 3) pbuf -= 3;
            const uint32_t dbase = sb + SV_OFF + (uint32_t)pbuf * VBYTES + vstBase;
            #pragma unroll
            for (int q = 0; q < 8; ++q)
                cpasync16(dbase + (uint32_t)(((uint32_t)q ^ vrl) << 4), gv + q * 8);
            cpasync_commit();
            gv += (size_t)BN * D;
        }

        // ---- softmax in registers (diagonal split); pack C-frags -> A-frags ----
        uint32_t pvA[8], pvB[8];
        if (jb != qb) {
            #pragma unroll
            for (int jt = 0; jt < 8; ++jt) {
                const float p00 = __expf(sacc[jt][0]);
                const float p01 = __expf(sacc[jt][1]);
                const float p10 = __expf(sacc[jt][2]);
                const float p11 = __expf(sacc[jt][3]);
                ls0 += p00 + p01;
                ls1 += p10 + p11;
                pvA[jt] = packh2(p00, p01);
                pvB[jt] = packh2(p10, p11);
            }
        } else {
            #pragma unroll
            for (int jt = 0; jt < 8; ++jt) {
                const int jc = jb * BN + jt * 8 + 2 * tg;
                float p00 = (jc     <= gi0) ? __expf(sacc[jt][0]) : 0.f;
                float p01 = (jc + 1 <= gi0) ? __expf(sacc[jt][1]) : 0.f;
                float p10 = (jc     <= gi1) ? __expf(sacc[jt][2]) : 0.f;
                float p11 = (jc + 1 <= gi1) ? __expf(sacc[jt][3]) : 0.f;
                ls0 += p00 + p01;
                ls1 += p10 + p11;
                pvA[jt] = packh2(p00, p01);
                pvB[jt] = packh2(p10, p11);
            }
        }

        // ---- GEMM2: O[16i x 128d] += P[16i x 64j] * V[64j x 128d] ----
        const uint32_t vtb = svc + rowA * 256;
        #pragma unroll
        for (int kt = 0; kt < 4; ++kt) {
            uint32_t bV[8][4];
            #pragma unroll
            for (int dp = 0; dp < 8; ++dp)
                ldsm4t(bV[dp], vtb + (uint32_t)kt * 4096 + remVT[dp]);
            const uint32_t a0 = pvA[2 * kt],     a1 = pvB[2 * kt];
            const uint32_t a2 = pvA[2 * kt + 1], a3 = pvB[2 * kt + 1];
            #pragma unroll
            for (int dg = 0; dg < 16; ++dg)
                mma16(oacc[dg], a0, a1, a2, a3,
                      bV[dg >> 1][(dg & 1) * 2], bV[dg >> 1][(dg & 1) * 2 + 1]);
        }

        // ---- V(jb+1) must be resident for the next iteration ----
        if (deep) cpasync_wait1();   // newest (V(jb+2)) may stay in flight
        else      cpasync_wait0();
        __syncthreads();

        if (++cur == 3) cur = 0;
    }

    // ---- epilogue: lsum reduce within quad (rows complete in-warp) ----
    ls0 += __shfl_xor_sync(0xffffffffu, ls0, 1);
    ls0 += __shfl_xor_sync(0xffffffffu, ls0, 2);
    ls1 += __shfl_xor_sync(0xffffffffu, ls1, 1);
    ls1 += __shfl_xor_sync(0xffffffffu, ls1, 2);
    const float inv0 = 1.f / ls0;
    const float inv1 = 1.f / ls1;

    float* o0 = Oh + (size_t)gi0 * D + 2 * tg;
    float* o1 = Oh + (size_t)gi1 * D + 2 * tg;
    #pragma unroll
    for (int dg = 0; dg < 16; ++dg) {
        float2 w0 = make_float2(oacc[dg][0] * inv0, oacc[dg][1] * inv0);
        float2 w1 = make_float2(oacc[dg][2] * inv1, oacc[dg][3] * inv1);
        *reinterpret_cast<float2*>(o0 + dg * 8) = w0;
        *reinterpret_cast<float2*>(o1 + dg * 8) = w1;
    }
}

}  // namespace

extern "C" void kernel_launch(void* const* d_in, const int* /*in_sizes*/, int /*n_in*/,
                              void* d_out, int /*out_size*/) {
    // inputs: d_in[0]=q (unused by reference), d_in[1]=k, d_in[2]=v
    const float* k = reinterpret_cast<const float*>(d_in[1]);
    const float* v = reinterpret_cast<const float*>(d_in[2]);
    float* o = reinterpret_cast<float*>(d_out);

    // pre-pass: V only (K' is converted per-CTA in the flash prologue)
    cvt16v<<<(unsigned)(NELEM / 4 / 256), 256>>>(v);

    cudaFuncSetAttribute(fa_r17,
                         cudaFuncAttributeMaxDynamicSharedMemorySize, SMEM_BYTES);
    dim3 grid(S / BM, 32);
    fa_r17<<<grid, NTHREADS, SMEM_BYTES>>>(k, o);
}